// round 16
// baseline (speedup 1.0000x reference)
#include <cuda_runtime.h>
#include <cuda_fp16.h>
#include <cstdint>

// out = tanh( Xa @ W1'^T + T[b] ),  T = s @ W2^T,  s[b] = sum_a x[b,a,:]
// W1' = Wh - Wc/7, W2 = Wc/7. fp16 HMMA, fp32 accum.
// 64-row tiles (8 batch rows), 256-thread CTAs, 3 CTAs/SM (<=85 regs).
// Warp (g=w>>1, c=w&1): rows g*16..g*16+15, cols c*32..c*32+31.
// Staging: warp w owns batch row w, lane owns one k-pair across agents ->
// s is a free in-register fp32 sum. ONE barrier per tile:
// [ GEMM(t) ; convert(t+1)+LDG(t+2) ; sync ; T-GEMM(t+1) ; epilogue(t) ]

#define NTILES 8192  // 524288 / 64

#define X0 0
#define X1 8192
#define S0 16384
#define S1 17408
#define T0 18432
#define T1 20480
#define SMEM_SZ 22528

__device__ __forceinline__ uint32_t smem_u32(const void* p) {
    uint32_t a;
    asm("{ .reg .u64 t; cvta.to.shared.u64 t, %1; cvt.u32.u64 %0, t; }"
        : "=r"(a) : "l"(p));
    return a;
}

__device__ __forceinline__ uint32_t pack_h2(float a, float b) {
    __half2 t = __float22half2_rn(make_float2(a, b));
    return *reinterpret_cast<uint32_t*>(&t);
}

__device__ __forceinline__ void mma_fp16(float* c, const uint32_t* a,
                                         uint32_t b0, uint32_t b1) {
    asm volatile(
        "mma.sync.aligned.m16n8k16.row.col.f32.f16.f16.f32 "
        "{%0,%1,%2,%3}, {%4,%5,%6,%7}, {%8,%9}, {%0,%1,%2,%3};"
        : "+f"(c[0]), "+f"(c[1]), "+f"(c[2]), "+f"(c[3])
        : "r"(a[0]), "r"(a[1]), "r"(a[2]), "r"(a[3]), "r"(b0), "r"(b1));
}

__device__ __forceinline__ void ldsm4(uint32_t* r, uint32_t addr) {
    asm volatile(
        "ldmatrix.sync.aligned.m8n8.x4.shared.b16 {%0,%1,%2,%3}, [%4];"
        : "=r"(r[0]), "=r"(r[1]), "=r"(r[2]), "=r"(r[3]) : "r"(addr));
}

__device__ __forceinline__ void ldsm2(uint32_t* r, uint32_t addr) {
    asm volatile(
        "ldmatrix.sync.aligned.m8n8.x2.shared.b16 {%0,%1}, [%2];"
        : "=r"(r[0]), "=r"(r[1]) : "r"(addr));
}

__device__ __forceinline__ float tanh_fast(float y) {
    float r;
    asm("tanh.approx.f32 %0, %1;" : "=f"(r) : "f"(y));
    return r;
}

__device__ __forceinline__ float2 ldcs2(const float2* p) {
    float2 v;
    asm volatile("ld.global.cs.v2.f32 {%0,%1}, [%2];"
                 : "=f"(v.x), "=f"(v.y) : "l"(p));
    return v;
}

__global__ void __launch_bounds__(256, 3)
comm_v15(const float* __restrict__ x, const float* __restrict__ Wh,
         const float* __restrict__ Wc, float* __restrict__ out) {
    __shared__ __align__(16) char sm[SMEM_SZ];
    const uint32_t sb = smem_u32(sm);

    const int tid = threadIdx.x;
    const int w = tid >> 5, lane = tid & 31;
    const int g = w >> 1, c = w & 1;
    const int q = lane >> 2, j = lane & 3;

    // ---- W1' B-frags in regs (32), permuted logical columns ----
    uint32_t bW[4][4][2];
#pragma unroll
    for (int ks = 0; ks < 4; ks++) {
#pragma unroll
        for (int nb = 0; nb < 4; nb++) {
            int n = (c << 5) + ((nb >> 1) << 4) + ((q >> 1) << 2) +
                    ((nb & 1) << 1) + (q & 1);
            int i00 = n * 64 + ks * 16 + j * 2;
            int i10 = i00 + 8;
            float w00 = Wh[i00] - Wc[i00] * (1.0f / 7.0f);
            float w01 = Wh[i00 + 1] - Wc[i00 + 1] * (1.0f / 7.0f);
            float w10 = Wh[i10] - Wc[i10] * (1.0f / 7.0f);
            float w11 = Wh[i10 + 1] - Wc[i10 + 1] * (1.0f / 7.0f);
            bW[ks][nb][0] = pack_h2(w00, w01);
            bW[ks][nb][1] = pack_h2(w10, w11);
        }
    }
    // ---- W2 B-frags for T-GEMM (8 regs): warp covers e-cols w*8..w*8+7 ----
    uint32_t bT[4][2];
#pragma unroll
    for (int ks = 0; ks < 4; ks++) {
        int n = (w << 3) + q;
        int i00 = n * 64 + ks * 16 + j * 2;
        int i10 = i00 + 8;
        bT[ks][0] = pack_h2(Wc[i00] * (1.0f / 7.0f), Wc[i00 + 1] * (1.0f / 7.0f));
        bT[ks][1] = pack_h2(Wc[i10] * (1.0f / 7.0f), Wc[i10 + 1] * (1.0f / 7.0f));
    }

    // ---- invariants ----
    const int arow = lane & 15, ahi = lane >> 4;
    const int r16 = (g << 4) + arow;           // main A row
    const uint32_t abase = (uint32_t)(r16 << 7);
    const int ar7 = r16 & 7;
    // staging: warp w = batch row w, lane = k-pair
    const uint32_t csw = (uint32_t)((((lane >> 2))) << 4) + ((lane & 3) << 2);
    // s-ldsm2 (lanes 0..15)
    const int tl = lane & 15, srow = tl & 7, shi = tl >> 3;

    const int grid = gridDim.x;
    int t = blockIdx.x, p = 0;

    // ================= prologue =================
    float2 v[8];
    {
        const float2* xp = (const float2*)(x + (size_t)t * 4096 + w * 512) + lane;
#pragma unroll
        for (int a = 0; a < 8; a++) v[a] = ldcs2(xp + a * 32);
        float sx = 0.f, sy = 0.f;
#pragma unroll
        for (int a = 0; a < 8; a++) {
            sx += v[a].x; sy += v[a].y;
            int r = (w << 3) + a;
            uint32_t ro = (uint32_t)(r << 7) + (csw ^ (uint32_t)((r & 7) << 4));
            *(uint32_t*)(sm + X0 + ro) = pack_h2(v[a].x, v[a].y);
        }
        uint32_t so = (uint32_t)(w << 7) + (csw ^ (uint32_t)((w & 7) << 4));
        *(uint32_t*)(sm + S0 + so) = pack_h2(sx, sy);
        if (t + grid < NTILES) {
            const float2* xn =
                (const float2*)(x + (size_t)(t + grid) * 4096 + w * 512) + lane;
#pragma unroll
            for (int a = 0; a < 8; a++) v[a] = ldcs2(xn + a * 32);
        }
    }
    __syncthreads();
    // T-GEMM(t0) -> T[0]
    {
        float accT[4] = {0.f, 0.f, 0.f, 0.f};
#pragma unroll
        for (int ks = 0; ks < 4; ks++) {
            uint32_t r2[2];
            ldsm2(r2, sb + S0 + (uint32_t)(srow << 7) +
                          ((((2 * ks + shi) ^ srow)) << 4));
            uint32_t a4[4] = {r2[0], 0u, r2[1], 0u};
            mma_fp16(accT, a4, bT[ks][0], bT[ks][1]);
        }
        float* Tb = (float*)(sm + T0);
        *(float2*)(Tb + q * 64 + (w << 3) + (j << 1)) =
            make_float2(accT[0], accT[1]);
    }

    // ============================ main loop ============================
    for (;;) {
        // ---- main GEMM(t): 4 ldsm4 + 16 MMA from X[p] ----
        float acc[4][4] = {};
        const uint32_t xbb = sb + (p ? X1 : X0);
#pragma unroll
        for (int ks = 0; ks < 4; ks++) {
            uint32_t a[4];
            ldsm4(a, xbb + abase + ((((2 * ks + ahi) ^ ar7)) << 4));
#pragma unroll
            for (int nb = 0; nb < 4; nb++)
                mma_fp16(acc[nb], a, bW[ks][nb][0], bW[ks][nb][1]);
        }

        int tn = t + grid;
        bool more = (tn < NTILES);

        // ---- convert(t+1) -> X[1-p], s[1-p]; prefetch(t+2) ----
        if (more) {
            char* xb = sm + (p ? X0 : X1);
            char* sf = sm + (p ? S0 : S1);
            float sx = 0.f, sy = 0.f;
#pragma unroll
            for (int a = 0; a < 8; a++) {
                sx += v[a].x; sy += v[a].y;
                int r = (w << 3) + a;
                uint32_t ro = (uint32_t)(r << 7) +
                              (csw ^ (uint32_t)((r & 7) << 4));
                *(uint32_t*)(xb + ro) = pack_h2(v[a].x, v[a].y);
            }
            uint32_t so = (uint32_t)(w << 7) + (csw ^ (uint32_t)((w & 7) << 4));
            *(uint32_t*)(sf + so) = pack_h2(sx, sy);
            if (tn + grid < NTILES) {
                const float2* xn = (const float2*)(
                    x + (size_t)(tn + grid) * 4096 + w * 512) + lane;
#pragma unroll
                for (int a = 0; a < 8; a++) v[a] = ldcs2(xn + a * 32);
            }
        }

        __syncthreads();  // the ONLY barrier per tile

        // ---- T-GEMM(t+1) -> T[1-p] ----
        if (more) {
            float accT[4] = {0.f, 0.f, 0.f, 0.f};
            const uint32_t sbase = sb + (p ? S0 : S1);
#pragma unroll
            for (int ks = 0; ks < 4; ks++) {
                uint32_t r2[2];
                ldsm2(r2, sbase + (uint32_t)(srow << 7) +
                              ((((2 * ks + shi) ^ srow)) << 4));
                uint32_t a4[4] = {r2[0], 0u, r2[1], 0u};
                mma_fp16(accT, a4, bT[ks][0], bT[ks][1]);
            }
            float* Tb = (float*)(sm + (p ? T0 : T1));
            *(float2*)(Tb + q * 64 + (w << 3) + (j << 1)) =
                make_float2(accT[0], accT[1]);
        }

        // ---- epilogue(t): +T[p] (broadcast LDS.128), tanh, streaming STG ----
        {
            const float* Tb = (const float*)(sm + (p ? T1 : T0));
#pragma unroll
            for (int h = 0; h < 2; h++) {
                int bb = 2 * g + h;
                int R = t * 64 + (g << 4) + (h << 3) + q;
                const float* Trow = Tb + bb * 64 + (c << 5) + (j << 2);
                float* op = out + (size_t)R * 64 + (c << 5) + (j << 2);
#pragma unroll
                for (int m = 0; m < 2; m++) {
                    float4 tv = *(const float4*)(Trow + m * 16);
                    float4 o;
                    o.x = tanh_fast(acc[2 * m][2 * h] + tv.x);
                    o.y = tanh_fast(acc[2 * m][2 * h + 1] + tv.y);
                    o.z = tanh_fast(acc[2 * m + 1][2 * h] + tv.z);
                    o.w = tanh_fast(acc[2 * m + 1][2 * h + 1] + tv.w);
                    __stcs((float4*)(op + m * 16), o);
                }
            }
        }

        if (!more) break;
        t = tn;
        p ^= 1;
    }
}

extern "C" void kernel_launch(void* const* d_in, const int* in_sizes, int n_in,
                              void* d_out, int out_size) {
    const float* x  = (const float*)d_in[0];
    const float* Wh = (const float*)d_in[1];
    const float* Wc = (const float*)d_in[2];
    float* out = (float*)d_out;

    int dev = 0, sms = 148;
    cudaGetDevice(&dev);
    cudaDeviceGetAttribute(&sms, cudaDevAttrMultiProcessorCount, dev);

    comm_v15<<<3 * sms, 256>>>(x, Wh, Wc, out);
}